// round 9
// baseline (speedup 1.0000x reference)
#include <cuda_runtime.h>
#include <cuda_bf16.h>
#include <math.h>
#include <stdint.h>
#include <mma.h>

using namespace nvcuda;

#define N_DST   20000
#define N_EDGE  200000
#define N_TOT   220000
#define DIM     128
#define HD      256

#define TILE_M  128
#define NT_SRC  1563          // ceil(200000/128); src rows [20000, 220000)
#define NT_DST  157           // ceil(20000/128)
#define NT      (NT_SRC + NT_DST)   // 1720
#define GEMM_GRID 148
#define GT      512

#define NBLK 128
#define BLKT 1024

// smem layout (bytes). Row strides chosen so stride/16B is odd => LDSM conflict-free.
#define LDAB 136              // bf16: 272B, /16 = 17 odd
#define LDBB 264              // bf16: 528B, /16 = 33 odd
#define LDC  264              // fp32 C staging
#define OFF_BBIG 0
#define OFF_BSML (OFF_BBIG + 128 * LDBB * 2)        // 67584
#define OFF_ABIG (OFF_BSML + 128 * LDBB * 2)        // 135168
#define OFF_ASML (OFF_ABIG + 128 * LDAB * 2)        // 169984
#define OFF_C    OFF_ABIG                            // sC (64 rows) aliases A after mainloop
#define OFF_RX   (OFF_ASML + 128 * LDAB * 2)        // 204800: rxs[128]
#define SMEM_BYTES (OFF_RX + 128 * 4)               // 205312

typedef unsigned long long u64;

// ---------------- scratch ----------------
__device__ __align__(16) float    g_el[N_TOT * HD];
__device__ __align__(16) float    g_er[N_DST * HD];
__device__ float    g_x2[N_TOT];
__device__ float    g_y2[N_DST];
__device__ float    g_ilms[N_TOT];
__device__ float    g_ilmd[N_DST];
__device__ float    g_qs[N_TOT * 2];
__device__ float    g_qr[N_DST * 2];
__device__ __align__(16) __nv_bfloat16 g_wsb[DIM * HD];
__device__ __align__(16) __nv_bfloat16 g_wss[DIM * HD];
__device__ __align__(16) __nv_bfloat16 g_wdb[DIM * HD];
__device__ __align__(16) __nv_bfloat16 g_wds[DIM * HD];
__device__ float    g_b2[2];
__device__ float    g_e[N_EDGE * 2];
__device__ float    g_inv[N_EDGE];
__device__ float    g_z2[N_EDGE * 2];
__device__ float    g_s1[N_DST];
__device__ float    g_s2[N_DST * 2];
__device__ unsigned g_m1[N_DST];
__device__ unsigned g_m2[N_DST * 2];
__device__ unsigned g_bar;

// ---------------- helpers ----------------
__device__ __forceinline__ unsigned fenc(float f) {
    unsigned u = __float_as_uint(f);
    return (u & 0x80000000u) ? ~u : (u | 0x80000000u);
}
__device__ __forceinline__ float fdec(unsigned u) {
    u = (u & 0x80000000u) ? (u & 0x7FFFFFFFu) : ~u;
    return __uint_as_float(u);
}
__device__ __forceinline__ float red32(float v) {
#pragma unroll
    for (int o = 16; o; o >>= 1) v += __shfl_xor_sync(0xffffffffu, v, o);
    return v;
}
__device__ __forceinline__ float red8(float v) {
    v += __shfl_xor_sync(0xffffffffu, v, 1);
    v += __shfl_xor_sync(0xffffffffu, v, 2);
    v += __shfl_xor_sync(0xffffffffu, v, 4);
    return v;
}

__device__ __forceinline__ void gridbar(unsigned target) {
    __syncthreads();
    if (threadIdx.x == 0) {
        __threadfence();
        atomicAdd(&g_bar, 1u);
        unsigned v;
        do {
            asm volatile("ld.acquire.gpu.b32 %0, [%1];" : "=r"(v) : "l"(&g_bar) : "memory");
        } while (v < target);
    }
    __syncthreads();
}

__global__ void bar_reset() { g_bar = 0u; }

// ---------------- init ----------------
__global__ void init_kernel(float* __restrict__ out) {
    int i = blockIdx.x * blockDim.x + threadIdx.x;
    int stride = gridDim.x * blockDim.x;
    for (int j = i; j < N_DST * HD / 4; j += stride) ((float4*)out)[j] = make_float4(0.f, 0.f, 0.f, 0.f);
    for (int j = i; j < N_DST; j += stride) { g_s1[j] = 0.f; g_m1[j] = 0u; }
    for (int j = i; j < 2 * N_DST; j += stride) { g_s2[j] = 0.f; g_m2[j] = 0u; }
}

// W transpose + bf16 split; bias norms (blocks 128,129)
__global__ void prep_wb(const float* __restrict__ w_src, const float* __restrict__ w_dst,
                        const float* __restrict__ b_src, const float* __restrict__ b_dst) {
    if (blockIdx.x < 128) {
        int i = blockIdx.x * 256 + threadIdx.x;
        int k = i >> 8, n = i & 255;
        float vs = w_src[n * DIM + k];
        float vd = w_dst[n * DIM + k];
        __nv_bfloat16 bs = __float2bfloat16(vs);
        g_wsb[i] = bs;
        g_wss[i] = __float2bfloat16(vs - __bfloat162float(bs));
        __nv_bfloat16 bd = __float2bfloat16(vd);
        g_wdb[i] = bd;
        g_wds[i] = __float2bfloat16(vd - __bfloat162float(bd));
    } else {
        int is_dst = blockIdx.x - 128;
        const float* b = is_dst ? b_dst : b_src;
        float v = b[threadIdx.x];
        v = v * v;
        v = red32(v);
        __shared__ float sred[8];
        if ((threadIdx.x & 31) == 0) sred[threadIdx.x >> 5] = v;
        __syncthreads();
        if (threadIdx.x == 0) {
            float s = 0.f;
#pragma unroll
            for (int w = 0; w < 8; w++) s += sred[w];
            g_b2[is_dst] = s;
        }
    }
}

// ---------------- persistent bf16-split GEMM with fused node-prep fill ----------------
__global__ void __launch_bounds__(GT, 1)
gemm_pers(const float* __restrict__ hyper, const float* __restrict__ dt,
          const float* __restrict__ time_w, const float* __restrict__ time_b,
          const float* __restrict__ bias_src, const float* __restrict__ bias_dst,
          const float* __restrict__ attn) {
    extern __shared__ char smem[];
    __nv_bfloat16* sBb = (__nv_bfloat16*)(smem + OFF_BBIG);
    __nv_bfloat16* sBs = (__nv_bfloat16*)(smem + OFF_BSML);
    __nv_bfloat16* sAb = (__nv_bfloat16*)(smem + OFF_ABIG);
    __nv_bfloat16* sAs = (__nv_bfloat16*)(smem + OFF_ASML);
    float* sC = (float*)(smem + OFF_C);     // aliases sAb/sAs after mainloop
    float* rxs = (float*)(smem + OFF_RX);   // per-row artanh(n)/n

    int tid = threadIdx.x;
    int wid = tid >> 5;
    int lane = tid & 31;
    int wr = wid >> 2, wc = wid & 3;        // 4x4 warp grid, warp tile 32x64
    int curW = -1;

    float4 tw = ((const float4*)time_w)[lane];
    float4 tb = ((const float4*)time_b)[lane];

    for (int t = blockIdx.x; t < NT; t += GEMM_GRID) {
        int is_dst = (t >= NT_SRC) ? 1 : 0;
        int row0 = is_dst ? (t - NT_SRC) * TILE_M : N_DST + t * TILE_M;
        int nbound = is_dst ? N_DST : N_TOT;

        if (is_dst != curW) {
            const __nv_bfloat16* gb = is_dst ? g_wdb : g_wsb;
            const __nv_bfloat16* gs = is_dst ? g_wds : g_wss;
            __syncthreads();
            for (int i = tid; i < 128 * 32; i += GT) {
                int r = i >> 5, c8 = i & 31;
                ((uint4*)(sBb + r * LDBB))[c8] = ((const uint4*)(gb + r * 256))[c8];
                ((uint4*)(sBs + r * LDBB))[c8] = ((const uint4*)(gs + r * 256))[c8];
            }
            curW = is_dst;
        }

        // fused fill: warp per row computes time-feat + projx + mobius_add, splits to bf16
#pragma unroll 2
        for (int it = 0; it < 8; it++) {
            int r = (tid >> 5) + it * 16;
            int gr = row0 + r;
            float4 sf = make_float4(0.f, 0.f, 0.f, 0.f);
            if (gr < nbound) {
                float tv = (gr < N_DST) ? 0.f : __ldg(&dt[gr - N_DST]);
                float4 tf;
                tf.x = cosf(fmaf(tv, tw.x, tb.x));
                tf.y = cosf(fmaf(tv, tw.y, tb.y));
                tf.z = cosf(fmaf(tv, tw.z, tb.z));
                tf.w = cosf(fmaf(tv, tw.w, tb.w));
                float y2 = red32(tf.x * tf.x + tf.y * tf.y + tf.z * tf.z + tf.w * tf.w);
                float n = sqrtf(fmaxf(y2, 1e-30f));
                if (n > 0.996f) {
                    float scp = 0.996f / n;
                    tf.x *= scp; tf.y *= scp; tf.z *= scp; tf.w *= scp;
                    y2 = y2 * scp * scp;
                }
                float4 x = __ldg(&((const float4*)hyper)[(size_t)gr * 32 + lane]);
                float x2 = red32(x.x * x.x + x.y * x.y + x.z * x.z + x.w * x.w);
                float xy = red32(x.x * tf.x + x.y * tf.y + x.z * tf.z + x.w * tf.w);
                float c1 = 1.f + 2.f * xy + y2;
                float c2 = 1.f - x2;
                float iden = 1.f / fmaxf(1.f + 2.f * xy + x2 * y2, 1e-15f);
                sf.x = (c1 * x.x + c2 * tf.x) * iden;
                sf.y = (c1 * x.y + c2 * tf.y) * iden;
                sf.z = (c1 * x.z + c2 * tf.z) * iden;
                sf.w = (c1 * x.w + c2 * tf.w) * iden;
                float xn2 = red32(sf.x * sf.x + sf.y * sf.y + sf.z * sf.z + sf.w * sf.w);
                if (lane == 0) {
                    float xn = sqrtf(fmaxf(xn2, 1e-30f));
                    rxs[r] = atanhf(fminf(xn, 0.9999999f)) / xn;
                }
            } else if (lane == 0) {
                rxs[r] = 0.f;
            }
            __nv_bfloat16 b0 = __float2bfloat16(sf.x);
            __nv_bfloat16 b1 = __float2bfloat16(sf.y);
            __nv_bfloat16 b2 = __float2bfloat16(sf.z);
            __nv_bfloat16 b3 = __float2bfloat16(sf.w);
            __nv_bfloat162* ab = (__nv_bfloat162*)(sAb + r * LDAB + lane * 4);
            __nv_bfloat162* as = (__nv_bfloat162*)(sAs + r * LDAB + lane * 4);
            ab[0] = __nv_bfloat162(b0, b1);
            ab[1] = __nv_bfloat162(b2, b3);
            as[0] = __nv_bfloat162(__float2bfloat16(sf.x - __bfloat162float(b0)),
                                   __float2bfloat16(sf.y - __bfloat162float(b1)));
            as[1] = __nv_bfloat162(__float2bfloat16(sf.z - __bfloat162float(b2)),
                                   __float2bfloat16(sf.w - __bfloat162float(b3)));
        }
        __syncthreads();

        wmma::fragment<wmma::accumulator, 16, 16, 16, float> acc[2][4];
#pragma unroll
        for (int mi = 0; mi < 2; mi++)
#pragma unroll
            for (int ni = 0; ni < 4; ni++) wmma::fill_fragment(acc[mi][ni], 0.f);

#pragma unroll 1
        for (int ks = 0; ks < 8; ks++) {
            wmma::fragment<wmma::matrix_a, 16, 16, 16, __nv_bfloat16, wmma::row_major> ab[2], as[2];
#pragma unroll
            for (int mi = 0; mi < 2; mi++) {
                wmma::load_matrix_sync(ab[mi], sAb + (wr * 32 + mi * 16) * LDAB + ks * 16, LDAB);
                wmma::load_matrix_sync(as[mi], sAs + (wr * 32 + mi * 16) * LDAB + ks * 16, LDAB);
            }
#pragma unroll
            for (int ni = 0; ni < 4; ni++) {
                wmma::fragment<wmma::matrix_b, 16, 16, 16, __nv_bfloat16, wmma::row_major> bb, bs;
                wmma::load_matrix_sync(bb, sBb + ks * 16 * LDBB + wc * 64 + ni * 16, LDBB);
                wmma::load_matrix_sync(bs, sBs + ks * 16 * LDBB + wc * 64 + ni * 16, LDBB);
#pragma unroll
                for (int mi = 0; mi < 2; mi++) {
                    wmma::mma_sync(acc[mi][ni], ab[mi], bs, acc[mi][ni]);
                    wmma::mma_sync(acc[mi][ni], as[mi], bb, acc[mi][ni]);
                    wmma::mma_sync(acc[mi][ni], ab[mi], bb, acc[mi][ni]);
                }
            }
        }

        const float* bias = is_dst ? bias_dst : bias_src;
        float b2v = g_b2[is_dst];
        float* eo_base = is_dst ? g_er : g_el;
        float* n2_out = is_dst ? g_y2 : g_x2;
        float* q_out = is_dst ? g_qr : g_qs;
        float* ilm_out = is_dst ? g_ilmd : g_ilms;

        // epilogue: two 64-row phases, sC aliases A region
#pragma unroll 1
        for (int h = 0; h < 2; h++) {
            __syncthreads();
            if ((wr >> 1) == h) {
#pragma unroll
                for (int mi = 0; mi < 2; mi++)
#pragma unroll
                    for (int ni = 0; ni < 4; ni++)
                        wmma::store_matrix_sync(sC + ((wr & 1) * 32 + mi * 16) * LDC + wc * 64 + ni * 16,
                                                acc[mi][ni], LDC, wmma::mem_row_major);
            }
            __syncthreads();

            int row = tid >> 3, q = tid & 7;   // 8 threads/row; thread q: cols q*4 + j*32
            int grow = row0 + h * 64 + row;
            bool live = (grow < nbound);

            float4 cv[8];
            float s = 0.f, p = 0.f;
#pragma unroll
            for (int j = 0; j < 8; j++) {
                float4 c = *(float4*)(sC + row * LDC + q * 4 + j * 32);
                float4 b = __ldg((const float4*)(bias + q * 4 + j * 32));
                cv[j] = c;
                s += c.x * c.x + c.y * c.y + c.z * c.z + c.w * c.w;
                p += c.x * b.x + c.y * b.y + c.z * b.z + c.w * b.w;
            }
            s = red8(s);
            p = red8(p);

            float mxn = sqrtf(fmaxf(s, 1e-30f));
            float rxv = live ? rxs[h * 64 + row] : 0.f;
            float sc = tanhf(mxn * rxv) / mxn;
            float xy = sc * p;
            float x2v = sc * sc * s;
            float c1 = 1.f + 2.f * xy + b2v;
            float c2 = 1.f - x2v;
            float iden = 1.f / fmaxf(1.f + 2.f * xy + x2v * b2v, 1e-15f);
            float k1 = c1 * sc;

            float fn2 = 0.f, r0 = 0.f, r1 = 0.f;
#pragma unroll
            for (int j = 0; j < 8; j++) {
                float4 b = __ldg((const float4*)(bias + q * 4 + j * 32));
                float4 a = __ldg((const float4*)(attn + q * 4 + j * 32));
                float4 f;
                f.x = (k1 * cv[j].x + c2 * b.x) * iden;
                f.y = (k1 * cv[j].y + c2 * b.y) * iden;
                f.z = (k1 * cv[j].z + c2 * b.z) * iden;
                f.w = (k1 * cv[j].w + c2 * b.w) * iden;
                cv[j] = f;
                fn2 += f.x * f.x + f.y * f.y + f.z * f.z + f.w * f.w;
                float rr = f.x * a.x + f.y * a.y + f.z * a.z + f.w * a.w;
                if (j < 4) r0 += rr; else r1 += rr;  // cols<128 = head0
            }
            fn2 = red8(fn2);
            r0 = red8(r0);
            r1 = red8(r1);

            float yn = sqrtf(fmaxf(fn2, 1e-30f));
            float at = atanhf(fminf(yn, 0.9999999f));
            float lm = at / yn;

            if (live) {
                float* eo = eo_base + (size_t)grow * HD + q * 4;
#pragma unroll
                for (int j = 0; j < 8; j++) {
                    float4 e;
                    e.x = lm * cv[j].x; e.y = lm * cv[j].y;
                    e.z = lm * cv[j].z; e.w = lm * cv[j].w;
                    *(float4*)(eo + j * 32) = e;
                }
                if (q == 0) {
                    n2_out[grow] = fn2;
                    ilm_out[grow] = yn / at;
                    q_out[grow * 2 + 0] = lm * r0;
                    q_out[grow * 2 + 1] = lm * r1;
                }
            }
        }
        __syncthreads();
    }
}

// ---------------- edge pass A (standalone, warp per edge) ----------------
__global__ void edgeA(const int* __restrict__ src_idx, const int* __restrict__ dst_idx) {
    int gid = blockIdx.x * blockDim.x + threadIdx.x;
    int e = gid >> 5, lane = gid & 31;
    if (e >= N_EDGE) return;
    int s = src_idx[e], t = dst_idx[e];
    const float4* fs = (const float4*)(g_el + (size_t)s * HD);
    const float4* fd = (const float4*)(g_er + (size_t)t * HD);
    float4 a0 = fs[lane], b0 = fd[lane];
    float4 a1 = fs[lane + 32], b1 = fd[lane + 32];
    float xy = a0.x * b0.x + a0.y * b0.y + a0.z * b0.z + a0.w * b0.w +
               a1.x * b1.x + a1.y * b1.y + a1.z * b1.z + a1.w * b1.w;
    xy = red32(xy);
    if (lane == 0) {
        xy = xy * g_ilms[s] * g_ilmd[t];
        float x2 = g_x2[s], y2 = g_y2[t];
        float A = 1.f - 2.f * xy + y2;
        float B = 1.f - x2;
        float num2 = A * A * x2 - 2.f * A * B * xy + B * B * y2;
        float den = fmaxf(1.f - 2.f * xy + x2 * y2, 1e-15f);
        float nn = sqrtf(fmaxf(num2 / (den * den), 1e-30f));
        float dist = 2.f * atanhf(fminf(nn, 0.9999999f));
        float inv = 1.f / (1e-15f + dist);
        g_inv[e] = inv;
        g_e[e * 2 + 0] = g_qs[s * 2 + 0] + g_qr[t * 2 + 0];
        g_e[e * 2 + 1] = g_qs[s * 2 + 1] + g_qr[t * 2 + 1];
        atomicMax(&g_m1[t], fenc(inv));
    }
}

// ---------------- fused edge phases B..E + finalize (persistent) ----------------
__global__ void __launch_bounds__(BLKT)
edge_fused(const int* __restrict__ src_idx, const int* __restrict__ dst_idx,
           float* __restrict__ out) {
    int gtid = blockIdx.x * BLKT + threadIdx.x;
    const int nthr = NBLK * BLKT;
    const int nw = nthr / 32;
    int wgl = gtid >> 5, lane = gtid & 31;

    int   tloc[2];
    float z1loc[2];
    float e2loc[2][2];

    // phase B
#pragma unroll
    for (int k = 0; k < 2; k++) {
        int e = gtid + k * nthr;
        if (e < N_EDGE) {
            int t = __ldg(&dst_idx[e]);
            tloc[k] = t;
            float z = expf(g_inv[e] - fdec(g_m1[t]));
            z1loc[k] = z;
            atomicAdd(&g_s1[t], z);
        }
    }
    gridbar(1 * NBLK);

    // phase C
#pragma unroll
    for (int k = 0; k < 2; k++) {
        int e = gtid + k * nthr;
        if (e < N_EDGE) {
            int t = tloc[k];
            float dsm = z1loc[k] / g_s1[t];
#pragma unroll
            for (int h = 0; h < 2; h++) {
                float v = g_e[e * 2 + h] * dsm;
                v = (v > 0.f) ? v : 0.2f * v;
                e2loc[k][h] = v;
                atomicMax(&g_m2[t * 2 + h], fenc(v));
            }
        }
    }
    gridbar(2 * NBLK);

    // phase D
#pragma unroll
    for (int k = 0; k < 2; k++) {
        int e = gtid + k * nthr;
        if (e < N_EDGE) {
            int t = tloc[k];
#pragma unroll
            for (int h = 0; h < 2; h++) {
                float z = expf(e2loc[k][h] - fdec(g_m2[t * 2 + h]));
                g_z2[e * 2 + h] = z;
                atomicAdd(&g_s2[t * 2 + h], z);
            }
        }
    }
    gridbar(3 * NBLK);

    // phase E: warp per edge
    for (int e = wgl; e < N_EDGE; e += nw) {
        int s = __ldg(&src_idx[e]);
        int t = __ldg(&dst_idx[e]);
        float a0 = g_z2[e * 2 + 0] / g_s2[t * 2 + 0];
        float a1 = g_z2[e * 2 + 1] / g_s2[t * 2 + 1];
        const float4* el = (const float4*)(g_el + (size_t)s * HD);
        float4 v0 = el[lane];
        float4 v1 = el[lane + 32];
        float* o = out + (size_t)t * HD + lane * 4;
        asm volatile("red.global.add.v4.f32 [%0], {%1, %2, %3, %4};"
                     :: "l"(o), "f"(v0.x * a0), "f"(v0.y * a0), "f"(v0.z * a0), "f"(v0.w * a0)
                     : "memory");
        asm volatile("red.global.add.v4.f32 [%0], {%1, %2, %3, %4};"
                     :: "l"(o + 128), "f"(v1.x * a1), "f"(v1.y * a1), "f"(v1.z * a1), "f"(v1.w * a1)
                     : "memory");
    }
    gridbar(4 * NBLK);

    // finalize: out = expmap0(out), warp per row
    for (int r = wgl; r < N_DST; r += nw) {
        float4* o = (float4*)(out + (size_t)r * HD);
        float4 u0 = o[lane], u1 = o[lane + 32];
        float s = u0.x * u0.x + u0.y * u0.y + u0.z * u0.z + u0.w * u0.w +
                  u1.x * u1.x + u1.y * u1.y + u1.z * u1.z + u1.w * u1.w;
        s = red32(s);
        float un = sqrtf(fmaxf(s, 1e-30f));
        float sc = tanhf(un) / un;
        u0.x *= sc; u0.y *= sc; u0.z *= sc; u0.w *= sc;
        u1.x *= sc; u1.y *= sc; u1.z *= sc; u1.w *= sc;
        o[lane] = u0;
        o[lane + 32] = u1;
    }
}

// ---------------- launch ----------------
extern "C" void kernel_launch(void* const* d_in, const int* in_sizes, int n_in,
                              void* d_out, int out_size) {
    const float* hyper  = (const float*)d_in[0];
    const float* dt     = (const float*)d_in[1];
    const float* time_w = (const float*)d_in[2];
    const float* time_b = (const float*)d_in[3];
    const float* w_src  = (const float*)d_in[4];
    const float* b_src  = (const float*)d_in[5];
    const float* w_dst  = (const float*)d_in[6];
    const float* b_dst  = (const float*)d_in[7];
    const float* attn   = (const float*)d_in[8];
    const int* src_idx  = (const int*)d_in[9];
    const int* dst_idx  = (const int*)d_in[10];
    float* out = (float*)d_out;

    (void)in_sizes; (void)n_in; (void)out_size;

    cudaFuncSetAttribute(gemm_pers, cudaFuncAttributeMaxDynamicSharedMemorySize, SMEM_BYTES);

    init_kernel<<<512, 256>>>(out);
    prep_wb<<<130, 256>>>(w_src, w_dst, b_src, b_dst);

    gemm_pers<<<GEMM_GRID, GT, SMEM_BYTES>>>(hyper, dt, time_w, time_b, b_src, b_dst, attn);

    edgeA<<<(N_EDGE * 32 + 255) / 256, 256>>>(src_idx, dst_idx);

    bar_reset<<<1, 1>>>();
    edge_fused<<<NBLK, BLKT>>>(src_idx, dst_idx, out);
}

// round 10
// speedup vs baseline: 1.0198x; 1.0198x over previous
#include <cuda_runtime.h>
#include <cuda_bf16.h>
#include <math.h>
#include <stdint.h>
#include <mma.h>

using namespace nvcuda;

#define N_DST   20000
#define N_EDGE  200000
#define N_TOT   220000
#define DIM     128
#define HD      256

#define TILE_M  128
#define NT_SRC  1563          // ceil(200000/128); src rows [20000, 220000)
#define NT_DST  157           // ceil(20000/128)
#define NT      (NT_SRC + NT_DST)   // 1720
#define GEMM_GRID 148
#define GT      512

#define NBLK 128
#define BLKT 1024

#define NP_BLOCKS 27500       // node-prep blocks (8 nodes each)
#define PREP_GRID (NP_BLOCKS + 130 + 512)

// smem layout (bytes). Row strides: stride/16B odd => LDSM conflict-free.
#define LDAB 136              // bf16: 272B, /16 = 17 odd
#define LDBB 264              // bf16: 528B, /16 = 33 odd
#define LDC  264              // fp32 C staging (64 rows, aliases A region)
#define OFF_BBIG 0
#define OFF_BSML (OFF_BBIG + 128 * LDBB * 2)        // 67584
#define OFF_ABIG (OFF_BSML + 128 * LDBB * 2)        // 135168
#define OFF_ASML (OFF_ABIG + 128 * LDAB * 2)        // 169984
#define OFF_C    OFF_ABIG
#define SMEM_BYTES (OFF_ASML + 128 * LDAB * 2)      // 204800

typedef unsigned long long u64;

// ---------------- scratch ----------------
__device__ __align__(16) __nv_bfloat16 g_afb[N_TOT * DIM];  // src_feat bf16 big
__device__ __align__(16) __nv_bfloat16 g_afs[N_TOT * DIM];  // src_feat bf16 small
__device__ float    g_rx[N_TOT];
__device__ __align__(16) float    g_el[N_TOT * HD];
__device__ __align__(16) float    g_er[N_DST * HD];
__device__ float    g_x2[N_TOT];
__device__ float    g_y2[N_DST];
__device__ float    g_ilms[N_TOT];
__device__ float    g_ilmd[N_DST];
__device__ float    g_qs[N_TOT * 2];
__device__ float    g_qr[N_DST * 2];
__device__ __align__(16) __nv_bfloat16 g_wsb[DIM * HD];
__device__ __align__(16) __nv_bfloat16 g_wss[DIM * HD];
__device__ __align__(16) __nv_bfloat16 g_wdb[DIM * HD];
__device__ __align__(16) __nv_bfloat16 g_wds[DIM * HD];
__device__ float    g_b2[2];
__device__ float    g_e[N_EDGE * 2];
__device__ float    g_inv[N_EDGE];
__device__ float    g_z2[N_EDGE * 2];
__device__ float    g_s1[N_DST];
__device__ float    g_s2[N_DST * 2];
__device__ unsigned g_m1[N_DST];
__device__ unsigned g_m2[N_DST * 2];
__device__ unsigned g_bar;

// ---------------- helpers ----------------
__device__ __forceinline__ unsigned fenc(float f) {
    unsigned u = __float_as_uint(f);
    return (u & 0x80000000u) ? ~u : (u | 0x80000000u);
}
__device__ __forceinline__ float fdec(unsigned u) {
    u = (u & 0x80000000u) ? (u & 0x7FFFFFFFu) : ~u;
    return __uint_as_float(u);
}
__device__ __forceinline__ float red32(float v) {
#pragma unroll
    for (int o = 16; o; o >>= 1) v += __shfl_xor_sync(0xffffffffu, v, o);
    return v;
}
__device__ __forceinline__ float red8(float v) {
    v += __shfl_xor_sync(0xffffffffu, v, 1);
    v += __shfl_xor_sync(0xffffffffu, v, 2);
    v += __shfl_xor_sync(0xffffffffu, v, 4);
    return v;
}

__device__ __forceinline__ void gridbar(unsigned target) {
    __syncthreads();
    if (threadIdx.x == 0) {
        __threadfence();
        atomicAdd(&g_bar, 1u);
        unsigned v;
        do {
            asm volatile("ld.acquire.gpu.b32 %0, [%1];" : "=r"(v) : "l"(&g_bar) : "memory");
        } while (v < target);
    }
    __syncthreads();
}

__global__ void bar_reset() { g_bar = 0u; }

// ---------------- fused prep: node_prep + W split + bias norms + init ----------------
__global__ void prep_all(const float* __restrict__ hyper, const float* __restrict__ dt,
                         const float* __restrict__ time_w, const float* __restrict__ time_b,
                         const float* __restrict__ w_src, const float* __restrict__ w_dst,
                         const float* __restrict__ b_src, const float* __restrict__ b_dst,
                         float* __restrict__ out) {
    int blk = blockIdx.x;
    if (blk < NP_BLOCKS) {
        // ---- node prep: warp per node, writes bf16-split A + rx ----
        int gid = blk * 256 + threadIdx.x;
        int node = gid >> 5, lane = gid & 31;
        if (node >= N_TOT) return;
        float4 tw = ((const float4*)time_w)[lane];
        float4 tb = ((const float4*)time_b)[lane];
        float t = (node < N_DST) ? 0.f : __ldg(&dt[node - N_DST]);
        float4 tf;
        tf.x = cosf(fmaf(t, tw.x, tb.x));
        tf.y = cosf(fmaf(t, tw.y, tb.y));
        tf.z = cosf(fmaf(t, tw.z, tb.z));
        tf.w = cosf(fmaf(t, tw.w, tb.w));
        float y2 = red32(tf.x * tf.x + tf.y * tf.y + tf.z * tf.z + tf.w * tf.w);
        float n = sqrtf(fmaxf(y2, 1e-30f));
        if (n > 0.996f) {
            float sc = 0.996f / n;
            tf.x *= sc; tf.y *= sc; tf.z *= sc; tf.w *= sc;
            y2 = y2 * sc * sc;
        }
        float4 x = ((const float4*)hyper)[(size_t)node * 32 + lane];
        float x2 = red32(x.x * x.x + x.y * x.y + x.z * x.z + x.w * x.w);
        float xy = red32(x.x * tf.x + x.y * tf.y + x.z * tf.z + x.w * tf.w);
        float c1 = 1.f + 2.f * xy + y2;
        float c2 = 1.f - x2;
        float iden = 1.f / fmaxf(1.f + 2.f * xy + x2 * y2, 1e-15f);
        float4 sf;
        sf.x = (c1 * x.x + c2 * tf.x) * iden;
        sf.y = (c1 * x.y + c2 * tf.y) * iden;
        sf.z = (c1 * x.z + c2 * tf.z) * iden;
        sf.w = (c1 * x.w + c2 * tf.w) * iden;
        // bf16 split
        __nv_bfloat16 b0 = __float2bfloat16(sf.x);
        __nv_bfloat16 b1 = __float2bfloat16(sf.y);
        __nv_bfloat16 b2 = __float2bfloat16(sf.z);
        __nv_bfloat16 b3 = __float2bfloat16(sf.w);
        __nv_bfloat162 pb0(b0, b1), pb1(b2, b3);
        __nv_bfloat162 ps0(__float2bfloat16(sf.x - __bfloat162float(b0)),
                           __float2bfloat16(sf.y - __bfloat162float(b1)));
        __nv_bfloat162 ps1(__float2bfloat16(sf.z - __bfloat162float(b2)),
                           __float2bfloat16(sf.w - __bfloat162float(b3)));
        uint2 ub, us;
        ub.x = *reinterpret_cast<unsigned*>(&pb0);
        ub.y = *reinterpret_cast<unsigned*>(&pb1);
        us.x = *reinterpret_cast<unsigned*>(&ps0);
        us.y = *reinterpret_cast<unsigned*>(&ps1);
        ((uint2*)g_afb)[(size_t)node * 32 + lane] = ub;
        ((uint2*)g_afs)[(size_t)node * 32 + lane] = us;
        float xn2 = red32(sf.x * sf.x + sf.y * sf.y + sf.z * sf.z + sf.w * sf.w);
        if (lane == 0) {
            float xn = sqrtf(fmaxf(xn2, 1e-30f));
            g_rx[node] = atanhf(fminf(xn, 0.9999999f)) / xn;
        }
    } else if (blk < NP_BLOCKS + 128) {
        // ---- W transpose + bf16 split ----
        int i = (blk - NP_BLOCKS) * 256 + threadIdx.x;
        int k = i >> 8, nn = i & 255;
        float vs = w_src[nn * DIM + k];
        float vd = w_dst[nn * DIM + k];
        __nv_bfloat16 bs = __float2bfloat16(vs);
        g_wsb[i] = bs;
        g_wss[i] = __float2bfloat16(vs - __bfloat162float(bs));
        __nv_bfloat16 bd = __float2bfloat16(vd);
        g_wdb[i] = bd;
        g_wds[i] = __float2bfloat16(vd - __bfloat162float(bd));
    } else if (blk < NP_BLOCKS + 130) {
        // ---- bias norms ----
        int is_dst = blk - NP_BLOCKS - 128;
        const float* b = is_dst ? b_dst : b_src;
        float v = b[threadIdx.x];
        v = v * v;
        v = red32(v);
        __shared__ float sred[8];
        if ((threadIdx.x & 31) == 0) sred[threadIdx.x >> 5] = v;
        __syncthreads();
        if (threadIdx.x == 0) {
            float s = 0.f;
#pragma unroll
            for (int w = 0; w < 8; w++) s += sred[w];
            g_b2[is_dst] = s;
        }
    } else {
        // ---- init (512 blocks, grid-stride) ----
        int i = (blk - NP_BLOCKS - 130) * 256 + threadIdx.x;
        int stride = 512 * 256;
        for (int j = i; j < N_DST * HD / 4; j += stride)
            ((float4*)out)[j] = make_float4(0.f, 0.f, 0.f, 0.f);
        for (int j = i; j < N_DST; j += stride) { g_s1[j] = 0.f; g_m1[j] = 0u; }
        for (int j = i; j < 2 * N_DST; j += stride) { g_s2[j] = 0.f; g_m2[j] = 0u; }
    }
}

// ---------------- persistent bf16-split GEMM (128x256xK128 tiles) ----------------
__global__ void __launch_bounds__(GT, 1)
gemm_pers(const float* __restrict__ bias_src, const float* __restrict__ bias_dst,
          const float* __restrict__ attn) {
    extern __shared__ char smem[];
    __nv_bfloat16* sBb = (__nv_bfloat16*)(smem + OFF_BBIG);
    __nv_bfloat16* sBs = (__nv_bfloat16*)(smem + OFF_BSML);
    __nv_bfloat16* sAb = (__nv_bfloat16*)(smem + OFF_ABIG);
    __nv_bfloat16* sAs = (__nv_bfloat16*)(smem + OFF_ASML);
    float* sC = (float*)(smem + OFF_C);   // 64 rows, aliases A region after mainloop

    int tid = threadIdx.x;
    int wid = tid >> 5;
    int wr = wid >> 2, wc = wid & 3;      // 4x4 warp grid, warp tile 32x64
    int curW = -1;

    for (int t = blockIdx.x; t < NT; t += GEMM_GRID) {
        int is_dst = (t >= NT_SRC) ? 1 : 0;
        int row0 = is_dst ? (t - NT_SRC) * TILE_M : N_DST + t * TILE_M;
        int nbound = is_dst ? N_DST : N_TOT;

        if (is_dst != curW) {
            const __nv_bfloat16* gb = is_dst ? g_wdb : g_wsb;
            const __nv_bfloat16* gs = is_dst ? g_wds : g_wss;
            __syncthreads();
            for (int i = tid; i < 128 * 32; i += GT) {
                int r = i >> 5, c8 = i & 31;
                ((uint4*)(sBb + r * LDBB))[c8] = ((const uint4*)(gb + r * 256))[c8];
                ((uint4*)(sBs + r * LDBB))[c8] = ((const uint4*)(gs + r * 256))[c8];
            }
            curW = is_dst;
        }

        // A fill: pure uint4 copy of pre-split bf16 (128 rows x 16 uint4 per matrix)
        for (int i = tid; i < 2048; i += GT) {
            int r = i >> 4, c = i & 15;
            int gr = row0 + r;
            uint4 vb = make_uint4(0u, 0u, 0u, 0u);
            uint4 vs = make_uint4(0u, 0u, 0u, 0u);
            if (gr < nbound) {
                vb = ((const uint4*)g_afb)[(size_t)gr * 16 + c];
                vs = ((const uint4*)g_afs)[(size_t)gr * 16 + c];
            }
            *(uint4*)(sAb + r * LDAB + c * 8) = vb;
            *(uint4*)(sAs + r * LDAB + c * 8) = vs;
        }
        __syncthreads();

        wmma::fragment<wmma::accumulator, 16, 16, 16, float> acc[2][4];
#pragma unroll
        for (int mi = 0; mi < 2; mi++)
#pragma unroll
            for (int ni = 0; ni < 4; ni++) wmma::fill_fragment(acc[mi][ni], 0.f);

#pragma unroll 1
        for (int ks = 0; ks < 8; ks++) {
            wmma::fragment<wmma::matrix_a, 16, 16, 16, __nv_bfloat16, wmma::row_major> ab[2], as[2];
#pragma unroll
            for (int mi = 0; mi < 2; mi++) {
                wmma::load_matrix_sync(ab[mi], sAb + (wr * 32 + mi * 16) * LDAB + ks * 16, LDAB);
                wmma::load_matrix_sync(as[mi], sAs + (wr * 32 + mi * 16) * LDAB + ks * 16, LDAB);
            }
#pragma unroll
            for (int ni = 0; ni < 4; ni++) {
                wmma::fragment<wmma::matrix_b, 16, 16, 16, __nv_bfloat16, wmma::row_major> bb, bs;
                wmma::load_matrix_sync(bb, sBb + ks * 16 * LDBB + wc * 64 + ni * 16, LDBB);
                wmma::load_matrix_sync(bs, sBs + ks * 16 * LDBB + wc * 64 + ni * 16, LDBB);
#pragma unroll
                for (int mi = 0; mi < 2; mi++) {
                    wmma::mma_sync(acc[mi][ni], ab[mi], bs, acc[mi][ni]);
                    wmma::mma_sync(acc[mi][ni], as[mi], bb, acc[mi][ni]);
                    wmma::mma_sync(acc[mi][ni], ab[mi], bb, acc[mi][ni]);
                }
            }
        }

        const float* bias = is_dst ? bias_dst : bias_src;
        float b2v = g_b2[is_dst];
        float* eo_base = is_dst ? g_er : g_el;
        float* n2_out = is_dst ? g_y2 : g_x2;
        float* q_out = is_dst ? g_qr : g_qs;
        float* ilm_out = is_dst ? g_ilmd : g_ilms;

        // epilogue: two 64-row phases, sC aliases A region
#pragma unroll 1
        for (int h = 0; h < 2; h++) {
            __syncthreads();
            if ((wr >> 1) == h) {
#pragma unroll
                for (int mi = 0; mi < 2; mi++)
#pragma unroll
                    for (int ni = 0; ni < 4; ni++)
                        wmma::store_matrix_sync(sC + ((wr & 1) * 32 + mi * 16) * LDC + wc * 64 + ni * 16,
                                                acc[mi][ni], LDC, wmma::mem_row_major);
            }
            __syncthreads();

            int row = tid >> 3, q = tid & 7;   // 8 threads/row; thread q: cols q*4 + j*32
            int grow = row0 + h * 64 + row;
            bool live = (grow < nbound);

            float4 cv[8];
            float s = 0.f, p = 0.f;
#pragma unroll
            for (int j = 0; j < 8; j++) {
                float4 c = *(float4*)(sC + row * LDC + q * 4 + j * 32);
                float4 b = __ldg((const float4*)(bias + q * 4 + j * 32));
                cv[j] = c;
                s += c.x * c.x + c.y * c.y + c.z * c.z + c.w * c.w;
                p += c.x * b.x + c.y * b.y + c.z * b.z + c.w * b.w;
            }
            s = red8(s);
            p = red8(p);

            float mxn = sqrtf(fmaxf(s, 1e-30f));
            float rxv = live ? __ldg(&g_rx[grow]) : 0.f;
            float sc = tanhf(mxn * rxv) / mxn;
            float xy = sc * p;
            float x2v = sc * sc * s;
            float c1 = 1.f + 2.f * xy + b2v;
            float c2 = 1.f - x2v;
            float iden = 1.f / fmaxf(1.f + 2.f * xy + x2v * b2v, 1e-15f);
            float k1 = c1 * sc;

            float fn2 = 0.f, r0 = 0.f, r1 = 0.f;
#pragma unroll
            for (int j = 0; j < 8; j++) {
                float4 b = __ldg((const float4*)(bias + q * 4 + j * 32));
                float4 a = __ldg((const float4*)(attn + q * 4 + j * 32));
                float4 f;
                f.x = (k1 * cv[j].x + c2 * b.x) * iden;
                f.y = (k1 * cv[j].y + c2 * b.y) * iden;
                f.z = (k1 * cv[j].z + c2 * b.z) * iden;
                f.w = (k1 * cv[j].w + c2 * b.w) * iden;
                cv[j] = f;
                fn2 += f.x * f.x + f.y * f.y + f.z * f.z + f.w * f.w;
                float rr = f.x * a.x + f.y * a.y + f.z * a.z + f.w * a.w;
                if (j < 4) r0 += rr; else r1 += rr;  // cols<128 = head0
            }
            fn2 = red8(fn2);
            r0 = red8(r0);
            r1 = red8(r1);

            float yn = sqrtf(fmaxf(fn2, 1e-30f));
            float at = atanhf(fminf(yn, 0.9999999f));
            float lm = at / yn;

            if (live) {
                float* eo = eo_base + (size_t)grow * HD + q * 4;
#pragma unroll
                for (int j = 0; j < 8; j++) {
                    float4 e;
                    e.x = lm * cv[j].x; e.y = lm * cv[j].y;
                    e.z = lm * cv[j].z; e.w = lm * cv[j].w;
                    *(float4*)(eo + j * 32) = e;
                }
                if (q == 0) {
                    n2_out[grow] = fn2;
                    ilm_out[grow] = yn / at;
                    q_out[grow * 2 + 0] = lm * r0;
                    q_out[grow * 2 + 1] = lm * r1;
                }
            }
        }
        __syncthreads();
    }
}

// ---------------- fused edge phases A..E + finalize (persistent) ----------------
__global__ void __launch_bounds__(BLKT)
edge_fused(const int* __restrict__ src_idx, const int* __restrict__ dst_idx,
           float* __restrict__ out) {
    int gtid = blockIdx.x * BLKT + threadIdx.x;
    const int nthr = NBLK * BLKT;
    const int nw = nthr / 32;
    int wgl = gtid >> 5, lane = gtid & 31;

    // ---- phase A: dot / ball_dist / e logits / segment max (warp per edge) ----
    for (int e = wgl; e < N_EDGE; e += nw) {
        int s = __ldg(&src_idx[e]);
        int t = __ldg(&dst_idx[e]);
        const float4* fs = (const float4*)(g_el + (size_t)s * HD);
        const float4* fd = (const float4*)(g_er + (size_t)t * HD);
        float4 a0 = fs[lane], b0 = fd[lane];
        float4 a1 = fs[lane + 32], b1 = fd[lane + 32];
        float xy = a0.x * b0.x + a0.y * b0.y + a0.z * b0.z + a0.w * b0.w +
                   a1.x * b1.x + a1.y * b1.y + a1.z * b1.z + a1.w * b1.w;
        xy = red32(xy);
        if (lane == 0) {
            xy = xy * g_ilms[s] * g_ilmd[t];
            float x2 = g_x2[s], y2 = g_y2[t];
            float A = 1.f - 2.f * xy + y2;
            float B = 1.f - x2;
            float num2 = A * A * x2 - 2.f * A * B * xy + B * B * y2;
            float den = fmaxf(1.f - 2.f * xy + x2 * y2, 1e-15f);
            float nn = sqrtf(fmaxf(num2 / (den * den), 1e-30f));
            float dist = 2.f * atanhf(fminf(nn, 0.9999999f));
            float inv = 1.f / (1e-15f + dist);
            g_inv[e] = inv;
            g_e[e * 2 + 0] = g_qs[s * 2 + 0] + g_qr[t * 2 + 0];
            g_e[e * 2 + 1] = g_qs[s * 2 + 1] + g_qr[t * 2 + 1];
            atomicMax(&g_m1[t], fenc(inv));
        }
    }
    gridbar(1 * NBLK);

    int   tloc[2];
    float z1loc[2];
    float e2loc[2][2];

    // ---- phase B ----
#pragma unroll
    for (int k = 0; k < 2; k++) {
        int e = gtid + k * nthr;
        if (e < N_EDGE) {
            int t = __ldg(&dst_idx[e]);
            tloc[k] = t;
            float z = expf(g_inv[e] - fdec(g_m1[t]));
            z1loc[k] = z;
            atomicAdd(&g_s1[t], z);
        }
    }
    gridbar(2 * NBLK);

    // ---- phase C ----
#pragma unroll
    for (int k = 0; k < 2; k++) {
        int e = gtid + k * nthr;
        if (e < N_EDGE) {
            int t = tloc[k];
            float dsm = z1loc[k] / g_s1[t];
#pragma unroll
            for (int h = 0; h < 2; h++) {
                float v = g_e[e * 2 + h] * dsm;
                v = (v > 0.f) ? v : 0.2f * v;
                e2loc[k][h] = v;
                atomicMax(&g_m2[t * 2 + h], fenc(v));
            }
        }
    }
    gridbar(3 * NBLK);

    // ---- phase D ----
#pragma unroll
    for (int k = 0; k < 2; k++) {
        int e = gtid + k * nthr;
        if (e < N_EDGE) {
            int t = tloc[k];
#pragma unroll
            for (int h = 0; h < 2; h++) {
                float z = expf(e2loc[k][h] - fdec(g_m2[t * 2 + h]));
                g_z2[e * 2 + h] = z;
                atomicAdd(&g_s2[t * 2 + h], z);
            }
        }
    }
    gridbar(4 * NBLK);

    // ---- phase E: warp per edge ----
    for (int e = wgl; e < N_EDGE; e += nw) {
        int s = __ldg(&src_idx[e]);
        int t = __ldg(&dst_idx[e]);
        float a0 = g_z2[e * 2 + 0] / g_s2[t * 2 + 0];
        float a1 = g_z2[e * 2 + 1] / g_s2[t * 2 + 1];
        const float4* el = (const float4*)(g_el + (size_t)s * HD);
        float4 v0 = el[lane];
        float4 v1 = el[lane + 32];
        float* o = out + (size_t)t * HD + lane * 4;
        asm volatile("red.global.add.v4.f32 [%0], {%1, %2, %3, %4};"
                     :: "l"(o), "f"(v0.x * a0), "f"(v0.y * a0), "f"(v0.z * a0), "f"(v0.w * a0)
                     : "memory");
        asm volatile("red.global.add.v4.f32 [%0], {%1, %2, %3, %4};"
                     :: "l"(o + 128), "f"(v1.x * a1), "f"(v1.y * a1), "f"(v1.z * a1), "f"(v1.w * a1)
                     : "memory");
    }
    gridbar(5 * NBLK);

    // ---- finalize: out = expmap0(out), warp per row ----
    for (int r = wgl; r < N_DST; r += nw) {
        float4* o = (float4*)(out + (size_t)r * HD);
        float4 u0 = o[lane], u1 = o[lane + 32];
        float s = u0.x * u0.x + u0.y * u0.y + u0.z * u0.z + u0.w * u0.w +
                  u1.x * u1.x + u1.y * u1.y + u1.z * u1.z + u1.w * u1.w;
        s = red32(s);
        float un = sqrtf(fmaxf(s, 1e-30f));
        float sc = tanhf(un) / un;
        u0.x *= sc; u0.y *= sc; u0.z *= sc; u0.w *= sc;
        u1.x *= sc; u1.y *= sc; u1.z *= sc; u1.w *= sc;
        o[lane] = u0;
        o[lane + 32] = u1;
    }
}

// ---------------- launch ----------------
extern "C" void kernel_launch(void* const* d_in, const int* in_sizes, int n_in,
                              void* d_out, int out_size) {
    const float* hyper  = (const float*)d_in[0];
    const float* dt     = (const float*)d_in[1];
    const float* time_w = (const float*)d_in[2];
    const float* time_b = (const float*)d_in[3];
    const float* w_src  = (const float*)d_in[4];
    const float* b_src  = (const float*)d_in[5];
    const float* w_dst  = (const float*)d_in[6];
    const float* b_dst  = (const float*)d_in[7];
    const float* attn   = (const float*)d_in[8];
    const int* src_idx  = (const int*)d_in[9];
    const int* dst_idx  = (const int*)d_in[10];
    float* out = (float*)d_out;

    (void)in_sizes; (void)n_in; (void)out_size;

    cudaFuncSetAttribute(gemm_pers, cudaFuncAttributeMaxDynamicSharedMemorySize, SMEM_BYTES);

    prep_all<<<PREP_GRID, 256>>>(hyper, dt, time_w, time_b, w_src, w_dst, b_src, b_dst, out);
    gemm_pers<<<GEMM_GRID, GT, SMEM_BYTES>>>(b_src, b_dst, attn);

    bar_reset<<<1, 1>>>();
    edge_fused<<<NBLK, BLKT>>>(src_idx, dst_idx, out);
}

// round 11
// speedup vs baseline: 1.2012x; 1.1779x over previous
#include <cuda_runtime.h>
#include <cuda_bf16.h>
#include <math.h>
#include <stdint.h>
#include <mma.h>

using namespace nvcuda;

#define N_DST   20000
#define N_EDGE  200000
#define N_TOT   220000
#define DIM     128
#define HD      256

#define TILE_M  128
#define NT_SRC  1563          // ceil(200000/128); src rows [20000, 220000)
#define NT_DST  157           // ceil(20000/128)
#define NT      (NT_SRC + NT_DST)   // 1720
#define GEMM_GRID 148
#define GT      512

#define NBLK 256
#define BLKT 1024

#define NP_BLOCKS 27500       // node-prep blocks (8 nodes each)
#define PREP_GRID (NP_BLOCKS + 130 + 512)

// smem layout (bytes). Row strides: stride/16B odd => LDSM conflict-free.
#define LDAB 136              // bf16: 272B, /16 = 17 odd
#define LDBB 264              // bf16: 528B, /16 = 33 odd
#define LDC  264              // fp32 C staging (64 rows, aliases A region)
#define OFF_BBIG 0
#define OFF_BSML (OFF_BBIG + 128 * LDBB * 2)        // 67584
#define OFF_ABIG (OFF_BSML + 128 * LDBB * 2)        // 135168
#define OFF_ASML (OFF_ABIG + 128 * LDAB * 2)        // 169984
#define OFF_C    OFF_ABIG
#define SMEM_BYTES (OFF_ASML + 128 * LDAB * 2)      // 204800

typedef unsigned long long u64;

// ---------------- scratch ----------------
__device__ __align__(16) __nv_bfloat16 g_afb[N_TOT * DIM];  // src_feat bf16 big
__device__ __align__(16) __nv_bfloat16 g_afs[N_TOT * DIM];  // src_feat bf16 small
__device__ float    g_rx[N_TOT];
__device__ __align__(16) float    g_el[N_TOT * HD];
__device__ __align__(16) float    g_er[N_DST * HD];
__device__ float    g_x2[N_TOT];
__device__ float    g_y2[N_DST];
__device__ float    g_ilms[N_TOT];
__device__ float    g_ilmd[N_DST];
__device__ float    g_qs[N_TOT * 2];
__device__ float    g_qr[N_DST * 2];
__device__ __align__(16) __nv_bfloat16 g_wsb[DIM * HD];
__device__ __align__(16) __nv_bfloat16 g_wss[DIM * HD];
__device__ __align__(16) __nv_bfloat16 g_wdb[DIM * HD];
__device__ __align__(16) __nv_bfloat16 g_wds[DIM * HD];
__device__ float    g_b2[2];
__device__ float    g_e[N_EDGE * 2];
__device__ float    g_inv[N_EDGE];
__device__ float    g_z2[N_EDGE * 2];
__device__ float    g_s1[N_DST];
__device__ float    g_s2[N_DST * 2];
__device__ unsigned g_m1[N_DST];
__device__ unsigned g_m2[N_DST * 2];
__device__ unsigned g_bar;

// ---------------- helpers ----------------
__device__ __forceinline__ unsigned fenc(float f) {
    unsigned u = __float_as_uint(f);
    return (u & 0x80000000u) ? ~u : (u | 0x80000000u);
}
__device__ __forceinline__ float fdec(unsigned u) {
    u = (u & 0x80000000u) ? (u & 0x7FFFFFFFu) : ~u;
    return __uint_as_float(u);
}
__device__ __forceinline__ float red32(float v) {
#pragma unroll
    for (int o = 16; o; o >>= 1) v += __shfl_xor_sync(0xffffffffu, v, o);
    return v;
}
__device__ __forceinline__ float red8(float v) {
    v += __shfl_xor_sync(0xffffffffu, v, 1);
    v += __shfl_xor_sync(0xffffffffu, v, 2);
    v += __shfl_xor_sync(0xffffffffu, v, 4);
    return v;
}

__device__ __forceinline__ void gridbar(unsigned target) {
    __syncthreads();
    if (threadIdx.x == 0) {
        __threadfence();
        atomicAdd(&g_bar, 1u);
        unsigned v;
        do {
            asm volatile("ld.acquire.gpu.b32 %0, [%1];" : "=r"(v) : "l"(&g_bar) : "memory");
        } while (v < target);
    }
    __syncthreads();
}

__global__ void bar_reset() { g_bar = 0u; }

// ---------------- fused prep: node_prep + W split + bias norms + init ----------------
__global__ void prep_all(const float* __restrict__ hyper, const float* __restrict__ dt,
                         const float* __restrict__ time_w, const float* __restrict__ time_b,
                         const float* __restrict__ w_src, const float* __restrict__ w_dst,
                         const float* __restrict__ b_src, const float* __restrict__ b_dst,
                         float* __restrict__ out) {
    int blk = blockIdx.x;
    if (blk < NP_BLOCKS) {
        // ---- node prep: warp per node, writes bf16-split A + rx ----
        int gid = blk * 256 + threadIdx.x;
        int node = gid >> 5, lane = gid & 31;
        if (node >= N_TOT) return;
        float4 tw = ((const float4*)time_w)[lane];
        float4 tb = ((const float4*)time_b)[lane];
        float t = (node < N_DST) ? 0.f : __ldg(&dt[node - N_DST]);
        float4 tf;
        tf.x = cosf(fmaf(t, tw.x, tb.x));
        tf.y = cosf(fmaf(t, tw.y, tb.y));
        tf.z = cosf(fmaf(t, tw.z, tb.z));
        tf.w = cosf(fmaf(t, tw.w, tb.w));
        float y2 = red32(tf.x * tf.x + tf.y * tf.y + tf.z * tf.z + tf.w * tf.w);
        float n = sqrtf(fmaxf(y2, 1e-30f));
        if (n > 0.996f) {
            float sc = 0.996f / n;
            tf.x *= sc; tf.y *= sc; tf.z *= sc; tf.w *= sc;
            y2 = y2 * sc * sc;
        }
        float4 x = ((const float4*)hyper)[(size_t)node * 32 + lane];
        float x2 = red32(x.x * x.x + x.y * x.y + x.z * x.z + x.w * x.w);
        float xy = red32(x.x * tf.x + x.y * tf.y + x.z * tf.z + x.w * tf.w);
        float c1 = 1.f + 2.f * xy + y2;
        float c2 = 1.f - x2;
        float iden = 1.f / fmaxf(1.f + 2.f * xy + x2 * y2, 1e-15f);
        float4 sf;
        sf.x = (c1 * x.x + c2 * tf.x) * iden;
        sf.y = (c1 * x.y + c2 * tf.y) * iden;
        sf.z = (c1 * x.z + c2 * tf.z) * iden;
        sf.w = (c1 * x.w + c2 * tf.w) * iden;
        __nv_bfloat16 b0 = __float2bfloat16(sf.x);
        __nv_bfloat16 b1 = __float2bfloat16(sf.y);
        __nv_bfloat16 b2 = __float2bfloat16(sf.z);
        __nv_bfloat16 b3 = __float2bfloat16(sf.w);
        __nv_bfloat162 pb0(b0, b1), pb1(b2, b3);
        __nv_bfloat162 ps0(__float2bfloat16(sf.x - __bfloat162float(b0)),
                           __float2bfloat16(sf.y - __bfloat162float(b1)));
        __nv_bfloat162 ps1(__float2bfloat16(sf.z - __bfloat162float(b2)),
                           __float2bfloat16(sf.w - __bfloat162float(b3)));
        uint2 ub, us;
        ub.x = *reinterpret_cast<unsigned*>(&pb0);
        ub.y = *reinterpret_cast<unsigned*>(&pb1);
        us.x = *reinterpret_cast<unsigned*>(&ps0);
        us.y = *reinterpret_cast<unsigned*>(&ps1);
        ((uint2*)g_afb)[(size_t)node * 32 + lane] = ub;
        ((uint2*)g_afs)[(size_t)node * 32 + lane] = us;
        float xn2 = red32(sf.x * sf.x + sf.y * sf.y + sf.z * sf.z + sf.w * sf.w);
        if (lane == 0) {
            float xn = sqrtf(fmaxf(xn2, 1e-30f));
            g_rx[node] = atanhf(fminf(xn, 0.9999999f)) / xn;
        }
    } else if (blk < NP_BLOCKS + 128) {
        // ---- W transpose + bf16 split ----
        int i = (blk - NP_BLOCKS) * 256 + threadIdx.x;
        int k = i >> 8, nn = i & 255;
        float vs = w_src[nn * DIM + k];
        float vd = w_dst[nn * DIM + k];
        __nv_bfloat16 bs = __float2bfloat16(vs);
        g_wsb[i] = bs;
        g_wss[i] = __float2bfloat16(vs - __bfloat162float(bs));
        __nv_bfloat16 bd = __float2bfloat16(vd);
        g_wdb[i] = bd;
        g_wds[i] = __float2bfloat16(vd - __bfloat162float(bd));
    } else if (blk < NP_BLOCKS + 130) {
        // ---- bias norms ----
        int is_dst = blk - NP_BLOCKS - 128;
        const float* b = is_dst ? b_dst : b_src;
        float v = b[threadIdx.x];
        v = v * v;
        v = red32(v);
        __shared__ float sred[8];
        if ((threadIdx.x & 31) == 0) sred[threadIdx.x >> 5] = v;
        __syncthreads();
        if (threadIdx.x == 0) {
            float s = 0.f;
#pragma unroll
            for (int w = 0; w < 8; w++) s += sred[w];
            g_b2[is_dst] = s;
        }
    } else {
        // ---- init (512 blocks, grid-stride) ----
        int i = (blk - NP_BLOCKS - 130) * 256 + threadIdx.x;
        int stride = 512 * 256;
        for (int j = i; j < N_DST * HD / 4; j += stride)
            ((float4*)out)[j] = make_float4(0.f, 0.f, 0.f, 0.f);
        for (int j = i; j < N_DST; j += stride) { g_s1[j] = 0.f; g_m1[j] = 0u; }
        for (int j = i; j < 2 * N_DST; j += stride) { g_s2[j] = 0.f; g_m2[j] = 0u; }
    }
}

// ---------------- persistent bf16-split GEMM (128x256xK128 tiles) ----------------
__global__ void __launch_bounds__(GT, 1)
gemm_pers(const float* __restrict__ bias_src, const float* __restrict__ bias_dst,
          const float* __restrict__ attn) {
    extern __shared__ char smem[];
    __nv_bfloat16* sBb = (__nv_bfloat16*)(smem + OFF_BBIG);
    __nv_bfloat16* sBs = (__nv_bfloat16*)(smem + OFF_BSML);
    __nv_bfloat16* sAb = (__nv_bfloat16*)(smem + OFF_ABIG);
    __nv_bfloat16* sAs = (__nv_bfloat16*)(smem + OFF_ASML);
    float* sC = (float*)(smem + OFF_C);   // 64 rows, aliases A region after mainloop

    int tid = threadIdx.x;
    int wid = tid >> 5;
    int wr = wid >> 2, wc = wid & 3;      // 4x4 warp grid, warp tile 32x64
    int curW = -1;

    for (int t = blockIdx.x; t < NT; t += GEMM_GRID) {
        int is_dst = (t >= NT_SRC) ? 1 : 0;
        int row0 = is_dst ? (t - NT_SRC) * TILE_M : N_DST + t * TILE_M;
        int nbound = is_dst ? N_DST : N_TOT;

        if (is_dst != curW) {
            const __nv_bfloat16* gb = is_dst ? g_wdb : g_wsb;
            const __nv_bfloat16* gs = is_dst ? g_wds : g_wss;
            __syncthreads();
            for (int i = tid; i < 128 * 32; i += GT) {
                int r = i >> 5, c8 = i & 31;
                ((uint4*)(sBb + r * LDBB))[c8] = ((const uint4*)(gb + r * 256))[c8];
                ((uint4*)(sBs + r * LDBB))[c8] = ((const uint4*)(gs + r * 256))[c8];
            }
            curW = is_dst;
        }

        // A fill: pure uint4 copy of pre-split bf16
        for (int i = tid; i < 2048; i += GT) {
            int r = i >> 4, c = i & 15;
            int gr = row0 + r;
            uint4 vb = make_uint4(0u, 0u, 0u, 0u);
            uint4 vs = make_uint4(0u, 0u, 0u, 0u);
            if (gr < nbound) {
                vb = ((const uint4*)g_afb)[(size_t)gr * 16 + c];
                vs = ((const uint4*)g_afs)[(size_t)gr * 16 + c];
            }
            *(uint4*)(sAb + r * LDAB + c * 8) = vb;
            *(uint4*)(sAs + r * LDAB + c * 8) = vs;
        }
        __syncthreads();

        wmma::fragment<wmma::accumulator, 16, 16, 16, float> acc[2][4];
#pragma unroll
        for (int mi = 0; mi < 2; mi++)
#pragma unroll
            for (int ni = 0; ni < 4; ni++) wmma::fill_fragment(acc[mi][ni], 0.f);

#pragma unroll 1
        for (int ks = 0; ks < 8; ks++) {
            wmma::fragment<wmma::matrix_a, 16, 16, 16, __nv_bfloat16, wmma::row_major> ab[2], as[2];
#pragma unroll
            for (int mi = 0; mi < 2; mi++) {
                wmma::load_matrix_sync(ab[mi], sAb + (wr * 32 + mi * 16) * LDAB + ks * 16, LDAB);
                wmma::load_matrix_sync(as[mi], sAs + (wr * 32 + mi * 16) * LDAB + ks * 16, LDAB);
            }
#pragma unroll
            for (int ni = 0; ni < 4; ni++) {
                wmma::fragment<wmma::matrix_b, 16, 16, 16, __nv_bfloat16, wmma::row_major> bb, bs;
                wmma::load_matrix_sync(bb, sBb + ks * 16 * LDBB + wc * 64 + ni * 16, LDBB);
                wmma::load_matrix_sync(bs, sBs + ks * 16 * LDBB + wc * 64 + ni * 16, LDBB);
#pragma unroll
                for (int mi = 0; mi < 2; mi++) {
                    wmma::mma_sync(acc[mi][ni], ab[mi], bs, acc[mi][ni]);
                    wmma::mma_sync(acc[mi][ni], as[mi], bb, acc[mi][ni]);
                    wmma::mma_sync(acc[mi][ni], ab[mi], bb, acc[mi][ni]);
                }
            }
        }

        const float* bias = is_dst ? bias_dst : bias_src;
        float b2v = g_b2[is_dst];
        float* eo_base = is_dst ? g_er : g_el;
        float* n2_out = is_dst ? g_y2 : g_x2;
        float* q_out = is_dst ? g_qr : g_qs;
        float* ilm_out = is_dst ? g_ilmd : g_ilms;

        // epilogue: two 64-row phases, sC aliases A region
#pragma unroll 1
        for (int h = 0; h < 2; h++) {
            __syncthreads();
            if ((wr >> 1) == h) {
#pragma unroll
                for (int mi = 0; mi < 2; mi++)
#pragma unroll
                    for (int ni = 0; ni < 4; ni++)
                        wmma::store_matrix_sync(sC + ((wr & 1) * 32 + mi * 16) * LDC + wc * 64 + ni * 16,
                                                acc[mi][ni], LDC, wmma::mem_row_major);
            }
            __syncthreads();

            int row = tid >> 3, q = tid & 7;   // 8 threads/row; thread q: cols q*4 + j*32
            int grow = row0 + h * 64 + row;
            bool live = (grow < nbound);

            float4 cv[8];
            float s = 0.f, p = 0.f;
#pragma unroll
            for (int j = 0; j < 8; j++) {
                float4 c = *(float4*)(sC + row * LDC + q * 4 + j * 32);
                float4 b = __ldg((const float4*)(bias + q * 4 + j * 32));
                cv[j] = c;
                s += c.x * c.x + c.y * c.y + c.z * c.z + c.w * c.w;
                p += c.x * b.x + c.y * b.y + c.z * b.z + c.w * b.w;
            }
            s = red8(s);
            p = red8(p);

            float mxn = sqrtf(fmaxf(s, 1e-30f));
            float rxv = live ? __ldg(&g_rx[grow]) : 0.f;
            float sc = tanhf(mxn * rxv) / mxn;
            float xy = sc * p;
            float x2v = sc * sc * s;
            float c1 = 1.f + 2.f * xy + b2v;
            float c2 = 1.f - x2v;
            float iden = 1.f / fmaxf(1.f + 2.f * xy + x2v * b2v, 1e-15f);
            float k1 = c1 * sc;

            float fn2 = 0.f, r0 = 0.f, r1 = 0.f;
#pragma unroll
            for (int j = 0; j < 8; j++) {
                float4 b = __ldg((const float4*)(bias + q * 4 + j * 32));
                float4 a = __ldg((const float4*)(attn + q * 4 + j * 32));
                float4 f;
                f.x = (k1 * cv[j].x + c2 * b.x) * iden;
                f.y = (k1 * cv[j].y + c2 * b.y) * iden;
                f.z = (k1 * cv[j].z + c2 * b.z) * iden;
                f.w = (k1 * cv[j].w + c2 * b.w) * iden;
                cv[j] = f;
                fn2 += f.x * f.x + f.y * f.y + f.z * f.z + f.w * f.w;
                float rr = f.x * a.x + f.y * a.y + f.z * a.z + f.w * a.w;
                if (j < 4) r0 += rr; else r1 += rr;  // cols<128 = head0
            }
            fn2 = red8(fn2);
            r0 = red8(r0);
            r1 = red8(r1);

            float yn = sqrtf(fmaxf(fn2, 1e-30f));
            float at = atanhf(fminf(yn, 0.9999999f));
            float lm = at / yn;

            if (live) {
                float* eo = eo_base + (size_t)grow * HD + q * 4;
#pragma unroll
                for (int j = 0; j < 8; j++) {
                    float4 e;
                    e.x = lm * cv[j].x; e.y = lm * cv[j].y;
                    e.z = lm * cv[j].z; e.w = lm * cv[j].w;
                    *(float4*)(eo + j * 32) = e;
                }
                if (q == 0) {
                    n2_out[grow] = fn2;
                    ilm_out[grow] = yn / at;
                    q_out[grow * 2 + 0] = lm * r0;
                    q_out[grow * 2 + 1] = lm * r1;
                }
            }
        }
        __syncthreads();
    }
}

// ---------------- edge pass A (standalone, warp per edge, high occupancy) ----------------
__global__ void edgeA(const int* __restrict__ src_idx, const int* __restrict__ dst_idx) {
    int gid = blockIdx.x * blockDim.x + threadIdx.x;
    int e = gid >> 5, lane = gid & 31;
    if (e >= N_EDGE) return;
    int s = src_idx[e], t = dst_idx[e];
    const float4* fs = (const float4*)(g_el + (size_t)s * HD);
    const float4* fd = (const float4*)(g_er + (size_t)t * HD);
    float4 a0 = fs[lane], b0 = fd[lane];
    float4 a1 = fs[lane + 32], b1 = fd[lane + 32];
    float xy = a0.x * b0.x + a0.y * b0.y + a0.z * b0.z + a0.w * b0.w +
               a1.x * b1.x + a1.y * b1.y + a1.z * b1.z + a1.w * b1.w;
    xy = red32(xy);
    if (lane == 0) {
        xy = xy * g_ilms[s] * g_ilmd[t];
        float x2 = g_x2[s], y2 = g_y2[t];
        float A = 1.f - 2.f * xy + y2;
        float B = 1.f - x2;
        float num2 = A * A * x2 - 2.f * A * B * xy + B * B * y2;
        float den = fmaxf(1.f - 2.f * xy + x2 * y2, 1e-15f);
        float nn = sqrtf(fmaxf(num2 / (den * den), 1e-30f));
        float dist = 2.f * atanhf(fminf(nn, 0.9999999f));
        float inv = 1.f / (1e-15f + dist);
        g_inv[e] = inv;
        g_e[e * 2 + 0] = g_qs[s * 2 + 0] + g_qr[t * 2 + 0];
        g_e[e * 2 + 1] = g_qs[s * 2 + 1] + g_qr[t * 2 + 1];
        atomicMax(&g_m1[t], fenc(inv));
    }
}

// ---------------- fused edge phases B..E + finalize (persistent, 256 blocks) ----------
__global__ void __launch_bounds__(BLKT, 2)
edge_fused(const int* __restrict__ src_idx, const int* __restrict__ dst_idx,
           float* __restrict__ out) {
    int gtid = blockIdx.x * BLKT + threadIdx.x;
    const int nthr = NBLK * BLKT;               // 262144 >= N_EDGE
    const int nw = nthr / 32;                   // 8192 warps
    int wgl = gtid >> 5, lane = gtid & 31;

    int   tloc = 0;
    float z1loc = 0.f;
    float e2loc[2];

    // ---- phase B: z1 = exp(inv - m1), segment sum ----
    if (gtid < N_EDGE) {
        int t = __ldg(&dst_idx[gtid]);
        tloc = t;
        float z = expf(g_inv[gtid] - fdec(g_m1[t]));
        z1loc = z;
        atomicAdd(&g_s1[t], z);
    }
    gridbar(1 * NBLK);

    // ---- phase C: dsm, leaky, segment max ----
    if (gtid < N_EDGE) {
        float dsm = z1loc / g_s1[tloc];
#pragma unroll
        for (int h = 0; h < 2; h++) {
            float v = g_e[gtid * 2 + h] * dsm;
            v = (v > 0.f) ? v : 0.2f * v;
            e2loc[h] = v;
            atomicMax(&g_m2[tloc * 2 + h], fenc(v));
        }
    }
    gridbar(2 * NBLK);

    // ---- phase D: z2 = exp(e2 - m2), segment sum ----
    if (gtid < N_EDGE) {
#pragma unroll
        for (int h = 0; h < 2; h++) {
            float z = expf(e2loc[h] - fdec(g_m2[tloc * 2 + h]));
            g_z2[gtid * 2 + h] = z;
            atomicAdd(&g_s2[tloc * 2 + h], z);
        }
    }
    gridbar(3 * NBLK);

    // ---- phase E: ft += el[src] * a (warp per edge, vector red) ----
    for (int e = wgl; e < N_EDGE; e += nw) {
        int s = __ldg(&src_idx[e]);
        int t = __ldg(&dst_idx[e]);
        float a0 = g_z2[e * 2 + 0] / g_s2[t * 2 + 0];
        float a1 = g_z2[e * 2 + 1] / g_s2[t * 2 + 1];
        const float4* el = (const float4*)(g_el + (size_t)s * HD);
        float4 v0 = el[lane];
        float4 v1 = el[lane + 32];
        float* o = out + (size_t)t * HD + lane * 4;
        asm volatile("red.global.add.v4.f32 [%0], {%1, %2, %3, %4};"
                     :: "l"(o), "f"(v0.x * a0), "f"(v0.y * a0), "f"(v0.z * a0), "f"(v0.w * a0)
                     : "memory");
        asm volatile("red.global.add.v4.f32 [%0], {%1, %2, %3, %4};"
                     :: "l"(o + 128), "f"(v1.x * a1), "f"(v1.y * a1), "f"(v1.z * a1), "f"(v1.w * a1)
                     : "memory");
    }
    gridbar(4 * NBLK);

    // ---- finalize: out = expmap0(out), warp per row ----
    for (int r = wgl; r < N_DST; r += nw) {
        float4* o = (float4*)(out + (size_t)r * HD);
        float4 u0 = o[lane], u1 = o[lane + 32];
        float s = u0.x * u0.x + u0.y * u0.y + u0.z * u0.z + u0.w * u0.w +
                  u1.x * u1.x + u1.y * u1.y + u1.z * u1.z + u1.w * u1.w;
        s = red32(s);
        float un = sqrtf(fmaxf(s, 1e-30f));
        float sc = tanhf(un) / un;
        u0.x *= sc; u0.y *= sc; u0.z *= sc; u0.w *= sc;
        u1.x *= sc; u1.y *= sc; u1.z *= sc; u1.w *= sc;
        o[lane] = u0;
        o[lane + 32] = u1;
    }
}

// ---------------- launch ----------------
extern "C" void kernel_launch(void* const* d_in, const int* in_sizes, int n_in,
                              void* d_out, int out_size) {
    const float* hyper  = (const float*)d_in[0];
    const float* dt     = (const float*)d_in[1];
    const float* time_w = (const float*)d_in[2];
    const float* time_b = (const float*)d_in[3];
    const float* w_src  = (const float*)d_in[4];
    const float* b_src  = (const float*)d_in[5];
    const float* w_dst  = (const float*)d_in[6];
    const float* b_dst  = (const float*)d_in[7];
    const float* attn   = (const float*)d_in[8];
    const int* src_idx  = (const int*)d_in[9];
    const int* dst_idx  = (const int*)d_in[10];
    float* out = (float*)d_out;

    (void)in_sizes; (void)n_in; (void)out_size;

    cudaFuncSetAttribute(gemm_pers, cudaFuncAttributeMaxDynamicSharedMemorySize, SMEM_BYTES);

    prep_all<<<PREP_GRID, 256>>>(hyper, dt, time_w, time_b, w_src, w_dst, b_src, b_dst, out);
    gemm_pers<<<GEMM_GRID, GT, SMEM_BYTES>>>(b_src, b_dst, attn);

    edgeA<<<(N_EDGE * 32 + 255) / 256, 256>>>(src_idx, dst_idx);

    bar_reset<<<1, 1>>>();
    edge_fused<<<NBLK, BLKT>>>(src_idx, dst_idx, out);
}

// round 12
// speedup vs baseline: 1.2374x; 1.0302x over previous
#include <cuda_runtime.h>
#include <cuda_bf16.h>
#include <math.h>
#include <stdint.h>
#include <mma.h>

using namespace nvcuda;

#define N_DST   20000
#define N_EDGE  200000
#define N_TOT   220000
#define DIM     128
#define HD      256

#define TILE_M  128
#define NT_SRC  1563          // ceil(200000/128); src rows [20000, 220000)
#define NT_DST  157           // ceil(20000/128)
#define NT      (NT_SRC + NT_DST)   // 1720
#define GEMM_GRID 148
#define GT      512

#define NBLK 256
#define BLKT 1024

#define NP_BLOCKS 27500       // node-prep blocks (8 nodes each)
#define PREP_GRID (NP_BLOCKS + 130 + 512)

// smem layout (bytes). Row strides: stride/16B odd => LDSM conflict-free.
#define LDAB 136              // bf16: 272B, /16 = 17 odd
#define LDBB 264              // bf16: 528B, /16 = 33 odd
#define LDC  264              // fp32 C staging (64 rows, aliases A region)
#define OFF_BBIG 0
#define OFF_BSML (OFF_BBIG + 128 * LDBB * 2)        // 67584
#define OFF_ABIG (OFF_BSML + 128 * LDBB * 2)        // 135168
#define OFF_ASML (OFF_ABIG + 128 * LDAB * 2)        // 169984
#define OFF_C    OFF_ABIG
#define SMEM_BYTES (OFF_ASML + 128 * LDAB * 2)      // 204800

typedef unsigned long long u64;

// ---------------- scratch (A arrays padded 64 rows for unconditional cp.async) ----------
__device__ __align__(16) __nv_bfloat16 g_afb[(N_TOT + 64) * DIM];
__device__ __align__(16) __nv_bfloat16 g_afs[(N_TOT + 64) * DIM];
__device__ float    g_rx[N_TOT];
__device__ __align__(16) float    g_el[N_TOT * HD];
__device__ __align__(16) float    g_er[N_DST * HD];
__device__ float    g_x2[N_TOT];
__device__ float    g_y2[N_DST];
__device__ float    g_ilms[N_TOT];
__device__ float    g_ilmd[N_DST];
__device__ float    g_qs[N_TOT * 2];
__device__ float    g_qr[N_DST * 2];
__device__ __align__(16) __nv_bfloat16 g_wsb[DIM * HD];
__device__ __align__(16) __nv_bfloat16 g_wss[DIM * HD];
__device__ __align__(16) __nv_bfloat16 g_wdb[DIM * HD];
__device__ __align__(16) __nv_bfloat16 g_wds[DIM * HD];
__device__ float    g_b2[2];
__device__ float    g_e[N_EDGE * 2];
__device__ float    g_inv[N_EDGE];
__device__ float    g_z2[N_EDGE * 2];
__device__ float    g_s1[N_DST];
__device__ float    g_s2[N_DST * 2];
__device__ unsigned g_m1[N_DST];
__device__ unsigned g_m2[N_DST * 2];
__device__ unsigned g_bar;

// ---------------- helpers ----------------
__device__ __forceinline__ unsigned fenc(float f) {
    unsigned u = __float_as_uint(f);
    return (u & 0x80000000u) ? ~u : (u | 0x80000000u);
}
__device__ __forceinline__ float fdec(unsigned u) {
    u = (u & 0x80000000u) ? (u & 0x7FFFFFFFu) : ~u;
    return __uint_as_float(u);
}
__device__ __forceinline__ float red32(float v) {
#pragma unroll
    for (int o = 16; o; o >>= 1) v += __shfl_xor_sync(0xffffffffu, v, o);
    return v;
}
__device__ __forceinline__ float red8(float v) {
    v += __shfl_xor_sync(0xffffffffu, v, 1);
    v += __shfl_xor_sync(0xffffffffu, v, 2);
    v += __shfl_xor_sync(0xffffffffu, v, 4);
    return v;
}
__device__ __forceinline__ void cp16(uint32_t saddr, const void* g) {
    asm volatile("cp.async.cg.shared.global [%0], [%1], 16;" :: "r"(saddr), "l"(g));
}

__device__ __forceinline__ void gridbar(unsigned target) {
    __syncthreads();
    if (threadIdx.x == 0) {
        __threadfence();
        atomicAdd(&g_bar, 1u);
        unsigned v;
        do {
            asm volatile("ld.acquire.gpu.b32 %0, [%1];" : "=r"(v) : "l"(&g_bar) : "memory");
        } while (v < target);
    }
    __syncthreads();
}

// ---------------- fused prep: node_prep + W split + bias norms + init ----------------
__global__ void prep_all(const float* __restrict__ hyper, const float* __restrict__ dt,
                         const float* __restrict__ time_w, const float* __restrict__ time_b,
                         const float* __restrict__ w_src, const float* __restrict__ w_dst,
                         const float* __restrict__ b_src, const float* __restrict__ b_dst,
                         float* __restrict__ out) {
    int blk = blockIdx.x;
    if (blk < NP_BLOCKS) {
        // ---- node prep: warp per node, writes bf16-split A + rx ----
        int gid = blk * 256 + threadIdx.x;
        int node = gid >> 5, lane = gid & 31;
        if (node >= N_TOT) return;
        float4 tw = ((const float4*)time_w)[lane];
        float4 tb = ((const float4*)time_b)[lane];
        float t = (node < N_DST) ? 0.f : __ldg(&dt[node - N_DST]);
        float4 tf;
        tf.x = cosf(fmaf(t, tw.x, tb.x));
        tf.y = cosf(fmaf(t, tw.y, tb.y));
        tf.z = cosf(fmaf(t, tw.z, tb.z));
        tf.w = cosf(fmaf(t, tw.w, tb.w));
        float y2 = red32(tf.x * tf.x + tf.y * tf.y + tf.z * tf.z + tf.w * tf.w);
        float n = sqrtf(fmaxf(y2, 1e-30f));
        if (n > 0.996f) {
            float sc = 0.996f / n;
            tf.x *= sc; tf.y *= sc; tf.z *= sc; tf.w *= sc;
            y2 = y2 * sc * sc;
        }
        float4 x = ((const float4*)hyper)[(size_t)node * 32 + lane];
        float x2 = red32(x.x * x.x + x.y * x.y + x.z * x.z + x.w * x.w);
        float xy = red32(x.x * tf.x + x.y * tf.y + x.z * tf.z + x.w * tf.w);
        float c1 = 1.f + 2.f * xy + y2;
        float c2 = 1.f - x2;
        float iden = 1.f / fmaxf(1.f + 2.f * xy + x2 * y2, 1e-15f);
        float4 sf;
        sf.x = (c1 * x.x + c2 * tf.x) * iden;
        sf.y = (c1 * x.y + c2 * tf.y) * iden;
        sf.z = (c1 * x.z + c2 * tf.z) * iden;
        sf.w = (c1 * x.w + c2 * tf.w) * iden;
        __nv_bfloat16 b0 = __float2bfloat16(sf.x);
        __nv_bfloat16 b1 = __float2bfloat16(sf.y);
        __nv_bfloat16 b2 = __float2bfloat16(sf.z);
        __nv_bfloat16 b3 = __float2bfloat16(sf.w);
        __nv_bfloat162 pb0(b0, b1), pb1(b2, b3);
        __nv_bfloat162 ps0(__float2bfloat16(sf.x - __bfloat162float(b0)),
                           __float2bfloat16(sf.y - __bfloat162float(b1)));
        __nv_bfloat162 ps1(__float2bfloat16(sf.z - __bfloat162float(b2)),
                           __float2bfloat16(sf.w - __bfloat162float(b3)));
        uint2 ub, us;
        ub.x = *reinterpret_cast<unsigned*>(&pb0);
        ub.y = *reinterpret_cast<unsigned*>(&pb1);
        us.x = *reinterpret_cast<unsigned*>(&ps0);
        us.y = *reinterpret_cast<unsigned*>(&ps1);
        ((uint2*)g_afb)[(size_t)node * 32 + lane] = ub;
        ((uint2*)g_afs)[(size_t)node * 32 + lane] = us;
        if (lane == 0) {
            // analytic ||sf||^2 = iden^2 (c1^2 x2 + 2 c1 c2 xy + c2^2 y2) — no 4th reduction
            float xn2 = iden * iden * (c1 * c1 * x2 + 2.f * c1 * c2 * xy + c2 * c2 * y2);
            float xn = sqrtf(fmaxf(xn2, 1e-30f));
            g_rx[node] = atanhf(fminf(xn, 0.9999999f)) / xn;
        }
    } else if (blk < NP_BLOCKS + 128) {
        // ---- W transpose + bf16 split ----
        int i = (blk - NP_BLOCKS) * 256 + threadIdx.x;
        int k = i >> 8, nn = i & 255;
        float vs = w_src[nn * DIM + k];
        float vd = w_dst[nn * DIM + k];
        __nv_bfloat16 bs = __float2bfloat16(vs);
        g_wsb[i] = bs;
        g_wss[i] = __float2bfloat16(vs - __bfloat162float(bs));
        __nv_bfloat16 bd = __float2bfloat16(vd);
        g_wdb[i] = bd;
        g_wds[i] = __float2bfloat16(vd - __bfloat162float(bd));
    } else if (blk < NP_BLOCKS + 130) {
        // ---- bias norms ----
        int is_dst = blk - NP_BLOCKS - 128;
        const float* b = is_dst ? b_dst : b_src;
        float v = b[threadIdx.x];
        v = v * v;
        v = red32(v);
        __shared__ float sred[8];
        if ((threadIdx.x & 31) == 0) sred[threadIdx.x >> 5] = v;
        __syncthreads();
        if (threadIdx.x == 0) {
            float s = 0.f;
#pragma unroll
            for (int w = 0; w < 8; w++) s += sred[w];
            g_b2[is_dst] = s;
        }
    } else {
        // ---- init (512 blocks, grid-stride) ----
        int i = (blk - NP_BLOCKS - 130) * 256 + threadIdx.x;
        int stride = 512 * 256;
        for (int j = i; j < N_DST * HD / 4; j += stride)
            ((float4*)out)[j] = make_float4(0.f, 0.f, 0.f, 0.f);
        for (int j = i; j < N_DST; j += stride) { g_s1[j] = 0.f; g_m1[j] = 0u; }
        for (int j = i; j < 2 * N_DST; j += stride) { g_s2[j] = 0.f; g_m2[j] = 0u; }
    }
}

// ---------------- persistent bf16-split GEMM (128x256xK128 tiles) ----------------
__global__ void __launch_bounds__(GT, 1)
gemm_pers(const float* __restrict__ bias_src, const float* __restrict__ bias_dst,
          const float* __restrict__ attn) {
    extern __shared__ char smem[];
    __nv_bfloat16* sBb = (__nv_bfloat16*)(smem + OFF_BBIG);
    __nv_bfloat16* sBs = (__nv_bfloat16*)(smem + OFF_BSML);
    __nv_bfloat16* sAb = (__nv_bfloat16*)(smem + OFF_ABIG);
    __nv_bfloat16* sAs = (__nv_bfloat16*)(smem + OFF_ASML);
    float* sC = (float*)(smem + OFF_C);   // 64 rows, aliases A region after mainloop

    uint32_t sAb_u = (uint32_t)__cvta_generic_to_shared(sAb);
    uint32_t sAs_u = (uint32_t)__cvta_generic_to_shared(sAs);

    int tid = threadIdx.x;
    int wid = tid >> 5;
    int wr = wid >> 2, wc = wid & 3;      // 4x4 warp grid, warp tile 32x64
    int curW = -1;

    for (int t = blockIdx.x; t < NT; t += GEMM_GRID) {
        int is_dst = (t >= NT_SRC) ? 1 : 0;
        int row0 = is_dst ? (t - NT_SRC) * TILE_M : N_DST + t * TILE_M;
        int nbound = is_dst ? N_DST : N_TOT;

        if (is_dst != curW) {
            const __nv_bfloat16* gb = is_dst ? g_wdb : g_wsb;
            const __nv_bfloat16* gs = is_dst ? g_wds : g_wss;
            __syncthreads();
            for (int i = tid; i < 128 * 32; i += GT) {
                int r = i >> 5, c8 = i & 31;
                ((uint4*)(sBb + r * LDBB))[c8] = ((const uint4*)(gb + r * 256))[c8];
                ((uint4*)(sBs + r * LDBB))[c8] = ((const uint4*)(gs + r * 256))[c8];
            }
            curW = is_dst;
        }

        // A fill: unconditional cp.async (arrays padded past N_TOT)
        for (int i = tid; i < 2048; i += GT) {
            int r = i >> 4, c = i & 15;
            size_t goff = (size_t)(row0 + r) * DIM + c * 8;   // bf16 elements
            cp16(sAb_u + r * (LDAB * 2) + c * 16, g_afb + goff);
            cp16(sAs_u + r * (LDAB * 2) + c * 16, g_afs + goff);
        }
        asm volatile("cp.async.commit_group;");
        asm volatile("cp.async.wait_group 0;" ::: "memory");
        __syncthreads();

        wmma::fragment<wmma::accumulator, 16, 16, 16, float> acc[2][4];
#pragma unroll
        for (int mi = 0; mi < 2; mi++)
#pragma unroll
            for (int ni = 0; ni < 4; ni++) wmma::fill_fragment(acc[mi][ni], 0.f);

#pragma unroll 1
        for (int ks = 0; ks < 8; ks++) {
            wmma::fragment<wmma::matrix_a, 16, 16, 16, __nv_bfloat16, wmma::row_major> ab[2], as[2];
#pragma unroll
            for (int mi = 0; mi < 2; mi++) {
                wmma::load_matrix_sync(ab[mi], sAb + (wr * 32 + mi * 16) * LDAB + ks * 16, LDAB);
                wmma::load_matrix_sync(as[mi], sAs + (wr * 32 + mi * 16) * LDAB + ks * 16, LDAB);
            }
#pragma unroll
            for (int ni = 0; ni < 4; ni++) {
                wmma::fragment<wmma::matrix_b, 16, 16, 16, __nv_bfloat16, wmma::row_major> bb, bs;
                wmma::load_matrix_sync(bb, sBb + ks * 16 * LDBB + wc * 64 + ni * 16, LDBB);
                wmma::load_matrix_sync(bs, sBs + ks * 16 * LDBB + wc * 64 + ni * 16, LDBB);
#pragma unroll
                for (int mi = 0; mi < 2; mi++) {
                    wmma::mma_sync(acc[mi][ni], ab[mi], bs, acc[mi][ni]);
                    wmma::mma_sync(acc[mi][ni], as[mi], bb, acc[mi][ni]);
                    wmma::mma_sync(acc[mi][ni], ab[mi], bb, acc[mi][ni]);
                }
            }
        }

        const float* bias = is_dst ? bias_dst : bias_src;
        float b2v = g_b2[is_dst];
        float* eo_base = is_dst ? g_er : g_el;
        float* n2_out = is_dst ? g_y2 : g_x2;
        float* q_out = is_dst ? g_qr : g_qs;
        float* ilm_out = is_dst ? g_ilmd : g_ilms;

        // epilogue: two 64-row phases, sC aliases A region
#pragma unroll 1
        for (int h = 0; h < 2; h++) {
            __syncthreads();
            if ((wr >> 1) == h) {
#pragma unroll
                for (int mi = 0; mi < 2; mi++)
#pragma unroll
                    for (int ni = 0; ni < 4; ni++)
                        wmma::store_matrix_sync(sC + ((wr & 1) * 32 + mi * 16) * LDC + wc * 64 + ni * 16,
                                                acc[mi][ni], LDC, wmma::mem_row_major);
            }
            __syncthreads();

            int row = tid >> 3, q = tid & 7;   // 8 threads/row; thread q: cols q*4 + j*32
            int grow = row0 + h * 64 + row;
            bool live = (grow < nbound);

            float4 cv[8];
            float s = 0.f, p = 0.f;
#pragma unroll
            for (int j = 0; j < 8; j++) {
                float4 c = *(float4*)(sC + row * LDC + q * 4 + j * 32);
                float4 b = __ldg((const float4*)(bias + q * 4 + j * 32));
                cv[j] = c;
                s += c.x * c.x + c.y * c.y + c.z * c.z + c.w * c.w;
                p += c.x * b.x + c.y * b.y + c.z * b.z + c.w * b.w;
            }
            s = red8(s);
            p = red8(p);

            float mxn = sqrtf(fmaxf(s, 1e-30f));
            float rxv = live ? __ldg(&g_rx[grow]) : 0.f;
            float sc = tanhf(mxn * rxv) / mxn;
            float xy = sc * p;
            float x2v = sc * sc * s;
            float c1 = 1.f + 2.f * xy + b2v;
            float c2 = 1.f - x2v;
            float iden = 1.f / fmaxf(1.f + 2.f * xy + x2v * b2v, 1e-15f);
            float k1 = c1 * sc;

            float fn2 = 0.f, r0 = 0.f, r1 = 0.f;
#pragma unroll
            for (int j = 0; j < 8; j++) {
                float4 b = __ldg((const float4*)(bias + q * 4 + j * 32));
                float4 a = __ldg((const float4*)(attn + q * 4 + j * 32));
                float4 f;
                f.x = (k1 * cv[j].x + c2 * b.x) * iden;
                f.y = (k1 * cv[j].y + c2 * b.y) * iden;
                f.z = (k1 * cv[j].z + c2 * b.z) * iden;
                f.w = (k1 * cv[j].w + c2 * b.w) * iden;
                cv[j] = f;
                fn2 += f.x * f.x + f.y * f.y + f.z * f.z + f.w * f.w;
                float rr = f.x * a.x + f.y * a.y + f.z * a.z + f.w * a.w;
                if (j < 4) r0 += rr; else r1 += rr;  // cols<128 = head0
            }
            fn2 = red8(fn2);
            r0 = red8(r0);
            r1 = red8(r1);

            float yn = sqrtf(fmaxf(fn2, 1e-30f));
            float at = atanhf(fminf(yn, 0.9999999f));
            float lm = at / yn;

            if (live) {
                float* eo = eo_base + (size_t)grow * HD + q * 4;
#pragma unroll
                for (int j = 0; j < 8; j++) {
                    float4 e;
                    e.x = lm * cv[j].x; e.y = lm * cv[j].y;
                    e.z = lm * cv[j].z; e.w = lm * cv[j].w;
                    *(float4*)(eo + j * 32) = e;
                }
                if (q == 0) {
                    n2_out[grow] = fn2;
                    ilm_out[grow] = yn / at;
                    q_out[grow * 2 + 0] = lm * r0;
                    q_out[grow * 2 + 1] = lm * r1;
                }
            }
        }
        __syncthreads();
    }
}

// ---------------- edge pass A (standalone, warp per edge, high occupancy) ----------------
__global__ void edgeA(const int* __restrict__ src_idx, const int* __restrict__ dst_idx) {
    int gid = blockIdx.x * blockDim.x + threadIdx.x;
    if (gid == 0) g_bar = 0u;      // reset grid barrier for edge_fused
    int e = gid >> 5, lane = gid & 31;
    if (e >= N_EDGE) return;
    int s = src_idx[e], t = dst_idx[e];
    const float4* fs = (const float4*)(g_el + (size_t)s * HD);
    const float4* fd = (const float4*)(g_er + (size_t)t * HD);
    float4 a0 = fs[lane], b0 = fd[lane];
    float4 a1 = fs[lane + 32], b1 = fd[lane + 32];
    float xy = a0.x * b0.x + a0.y * b0.y + a0.z * b0.z + a0.w * b0.w +
               a1.x * b1.x + a1.y * b1.y + a1.z * b1.z + a1.w * b1.w;
    xy = red32(xy);
    if (lane == 0) {
        xy = xy * g_ilms[s] * g_ilmd[t];
        float x2 = g_x2[s], y2 = g_y2[t];
        float A = 1.f - 2.f * xy + y2;
        float B = 1.f - x2;
        float num2 = A * A * x2 - 2.f * A * B * xy + B * B * y2;
        float den = fmaxf(1.f - 2.f * xy + x2 * y2, 1e-15f);
        float nn = sqrtf(fmaxf(num2 / (den * den), 1e-30f));
        float dist = 2.f * atanhf(fminf(nn, 0.9999999f));
        float inv = 1.f / (1e-15f + dist);
        g_inv[e] = inv;
        g_e[e * 2 + 0] = g_qs[s * 2 + 0] + g_qr[t * 2 + 0];
        g_e[e * 2 + 1] = g_qs[s * 2 + 1] + g_qr[t * 2 + 1];
        atomicMax(&g_m1[t], fenc(inv));
    }
}

// ---------------- fused edge phases B..E + finalize (persistent, 256 blocks) ----------
__global__ void __launch_bounds__(BLKT, 2)
edge_fused(const int* __restrict__ src_idx, const int* __restrict__ dst_idx,
           float* __restrict__ out) {
    int gtid = blockIdx.x * BLKT + threadIdx.x;
    const int nthr = NBLK * BLKT;               // 262144 >= N_EDGE
    const int nw = nthr / 32;                   // 8192 warps
    int wgl = gtid >> 5, lane = gtid & 31;

    int   tloc = 0;
    float z1loc = 0.f;
    float e2loc[2];

    // ---- phase B: z1 = exp(inv - m1), segment sum ----
    if (gtid < N_EDGE) {
        int t = __ldg(&dst_idx[gtid]);
        tloc = t;
        float z = expf(g_inv[gtid] - fdec(g_m1[t]));
        z1loc = z;
        atomicAdd(&g_s1[t], z);
    }
    gridbar(1 * NBLK);

    // ---- phase C: dsm, leaky, segment max ----
    if (gtid < N_EDGE) {
        float dsm = z1loc / g_s1[tloc];
#pragma unroll
        for (int h = 0; h < 2; h++) {
            float v = g_e[gtid * 2 + h] * dsm;
            v = (v > 0.f) ? v : 0.2f * v;
            e2loc[h] = v;
            atomicMax(&g_m2[tloc * 2 + h], fenc(v));
        }
    }
    gridbar(2 * NBLK);

    // ---- phase D: z2 = exp(e2 - m2), segment sum ----
    if (gtid < N_EDGE) {
#pragma unroll
        for (int h = 0; h < 2; h++) {
            float z = expf(e2loc[h] - fdec(g_m2[tloc * 2 + h]));
            g_z2[gtid * 2 + h] = z;
            atomicAdd(&g_s2[tloc * 2 + h], z);
        }
    }
    gridbar(3 * NBLK);

    // ---- phase E: ft += el[src] * a (warp per edge, vector red) ----
    for (int e = wgl; e < N_EDGE; e += nw) {
        int s = __ldg(&src_idx[e]);
        int t = __ldg(&dst_idx[e]);
        float a0 = g_z2[e * 2 + 0] / g_s2[t * 2 + 0];
        float a1 = g_z2[e * 2 + 1] / g_s2[t * 2 + 1];
        const float4* el = (const float4*)(g_el + (size_t)s * HD);
        float4 v0 = el[lane];
        float4 v1 = el[lane + 32];
        float* o = out + (size_t)t * HD + lane * 4;
        asm volatile("red.global.add.v4.f32 [%0], {%1, %2, %3, %4};"
                     :: "l"(o), "f"(v0.x * a0), "f"(v0.y * a0), "f"(v0.z * a0), "f"(v0.w * a0)
                     : "memory");
        asm volatile("red.global.add.v4.f32 [%0], {%1, %2, %3, %4};"
                     :: "l"(o + 128), "f"(v1.x * a1), "f"(v1.y * a1), "f"(v1.z * a1), "f"(v1.w * a1)
                     : "memory");
    }
    gridbar(4 * NBLK);

    // ---- finalize: out = expmap0(out), warp per row ----
    for (int r = wgl; r < N_DST; r += nw) {
        float4* o = (float4*)(out + (size_t)r * HD);
        float4 u0 = o[lane], u1 = o[lane + 32];
        float s = u0.x * u0.x + u0.y * u0.y + u0.z * u0.z + u0.w * u0.w +
                  u1.x * u1.x + u1.y * u1.y + u1.z * u1.z + u1.w * u1.w;
        s = red32(s);
        float un = sqrtf(fmaxf(s, 1e-30f));
        float sc = tanhf(un) / un;
        u0.x *= sc; u0.y *= sc; u0.z *= sc; u0.w *= sc;
        u1.x *= sc; u1.y *= sc; u1.z *= sc; u1.w *= sc;
        o[lane] = u0;
        o[lane + 32] = u1;
    }
}

// ---------------- launch ----------------
extern "C" void kernel_launch(void* const* d_in, const int* in_sizes, int n_in,
                              void* d_out, int out_size) {
    const float* hyper  = (const float*)d_in[0];
    const float* dt     = (const float*)d_in[1];
    const float* time_w = (const float*)d_in[2];
    const float* time_b = (const float*)d_in[3];
    const float* w_src  = (const float*)d_in[4];
    const float* b_src  = (const float*)d_in[5];
    const float* w_dst  = (const float*)d_in[6];
    const float* b_dst  = (const float*)d_in[7];
    const float* attn   = (const float*)d_in[8];
    const int* src_idx  = (const int*)d_in[9];
    const int* dst_idx  = (const int*)d_in[10];
    float* out = (float*)d_out;

    (void)in_sizes; (void)n_in; (void)out_size;

    cudaFuncSetAttribute(gemm_pers, cudaFuncAttributeMaxDynamicSharedMemorySize, SMEM_BYTES);

    prep_all<<<PREP_GRID, 256>>>(hyper, dt, time_w, time_b, w_src, w_dst, b_src, b_dst, out);
    gemm_pers<<<GEMM_GRID, GT, SMEM_BYTES>>>(b_src, b_dst, attn);

    edgeA<<<(N_EDGE * 32 + 255) / 256, 256>>>(src_idx, dst_idx);

    edge_fused<<<NBLK, BLKT>>>(src_idx, dst_idx, out);
}